// round 7
// baseline (speedup 1.0000x reference)
#include <cuda_runtime.h>
#include <cstdint>
#include <cstddef>

// Problem constants
#define NUM_LUT 3
#define GDIM    1024      // G = IN_F / VEC
#define OUTF    4096
#define SLUT    16
#define VEC     4
#define NGRP    32        // NG = IN_F / GROUP (GROUP = 32 g's)

// Tiling: block = 8 warps; each warp owns 8 consecutive o's; block loops 8 g's.
#define NTHREADS 256
#define O_PER_WARP 8
#define OTILE (8 * O_PER_WARP)   // 64 o per block
#define GTILE_J 8                // g's per block (8 | 32 -> single quant group per block)

// Per-LUT: local first-max argmax over this lane's 4 floats, then quad-wide
// reduction via redux.sync (2 MIO ops instead of 4 shfls + merges).
// Exact first-occurrence tie-break: lanes whose local max equals the quad max
// offer their global index; min wins. Bit-exact vs jnp.argmax.
#define DO_LUT(v, L, g, accv)                                                 \
    {                                                                         \
        float m = (v).x; int mi = 0;                                          \
        if ((v).y > m) { m = (v).y; mi = 1; }                                 \
        if ((v).z > m) { m = (v).z; mi = 2; }                                 \
        if ((v).w > m) { m = (v).w; mi = 3; }                                 \
        unsigned um = __float_as_uint(m);                                     \
        um ^= (unsigned)((int)um >> 31) | 0x80000000u;  /* orderable uint */  \
        const unsigned qm = __reduce_max_sync(quadmask, um);                  \
        unsigned li = (um == qm) ? (unsigned)(part * 4 + mi) : 63u;           \
        li = __reduce_min_sync(quadmask, li);                                 \
        (accv) += __ldg(cbk + (((size_t)(L) * GDIM + (g)) * SLUT + li) * VEC + part); \
    }

__global__ void __launch_bounds__(NTHREADS)
recon_kernel(const float* __restrict__ gate,
             const float* __restrict__ codebook,
             const float* __restrict__ scales,
             const int*   __restrict__ zeros,
             float*       __restrict__ out)
{
    const int tid    = threadIdx.x;
    const int wid    = tid >> 5;
    const int lane   = tid & 31;
    const int part   = lane & 3;              // which 16B quarter of the 64B gate row
    const unsigned quadmask = 0xFu << (lane & 28);

    const int o0     = blockIdx.x * OTILE + wid * O_PER_WARP;  // warp's first o
    const int o      = o0 + (lane >> 2);
    const int g0     = blockIdx.y * GTILE_J;
    const int ng     = blockIdx.y >> 2;       // quant group (8*4 = 32 g's per group)

    const float sc   = scales[o * NGRP + ng];
    const float bias = -((float)zeros[o * NGRP + ng]) * sc;  // out = acc*sc + bias

    // Gate base pointers (float4 units). For fixed (l,g): warp covers
    // o0..o0+7 -> one contiguous 512B chunk; lane q reads float4 #q.
    const float4* gp0 = reinterpret_cast<const float4*>(gate) +
        (((size_t)0 * GDIM + g0) * OUTF + o0) * (SLUT / 4) + lane;
    const float4* gp1 = reinterpret_cast<const float4*>(gate) +
        (((size_t)1 * GDIM + g0) * OUTF + o0) * (SLUT / 4) + lane;
    const float4* gp2 = reinterpret_cast<const float4*>(gate) +
        (((size_t)2 * GDIM + g0) * OUTF + o0) * (SLUT / 4) + lane;
    const size_t gstep = (size_t)OUTF * SLUT / 4;   // 16384 float4 per g

    const float* cbk = codebook;

    float* outrow = out + (size_t)o * (GDIM * VEC) + part;  // + g*4 per step

    #pragma unroll 2
    for (int j = 0; j < GTILE_J; ++j) {
        const int g = g0 + j;

        // Issue all three contiguous 512B streaming loads up front
        const float4 v0 = __ldcs(gp0 + (size_t)j * gstep);
        const float4 v1 = __ldcs(gp1 + (size_t)j * gstep);
        const float4 v2 = __ldcs(gp2 + (size_t)j * gstep);

        float acc = 0.0f;
        DO_LUT(v0, 0, g, acc)
        DO_LUT(v1, 1, g, acc)
        DO_LUT(v2, 2, g, acc)

        // Lane owns one output component; quad writes 16B contiguous; over the
        // 8-g tile each quad fills its 128B output line -> clean L2 merge.
        __stcs(outrow + g * VEC, fmaf(acc, sc, bias));
    }
}

extern "C" void kernel_launch(void* const* d_in, const int* in_sizes, int n_in,
                              void* d_out, int out_size) {
    const float* gate     = (const float*)d_in[0];  // [3,1024,4096,16] f32
    const float* codebook = (const float*)d_in[1];  // [3,1024,16,4]   f32
    const float* scales   = (const float*)d_in[2];  // [4096,32]       f32
    const int*   zeros    = (const int*)  d_in[3];  // [4096,32]       i32
    float*       out      = (float*)d_out;          // [4096,4096]     f32

    (void)in_sizes; (void)n_in; (void)out_size;

    dim3 grid(OUTF / OTILE, GDIM / GTILE_J);   // (64, 128) = 8192 blocks
    recon_kernel<<<grid, NTHREADS>>>(gate, codebook, scales, zeros, out);
}

// round 8
// speedup vs baseline: 2.4067x; 2.4067x over previous
#include <cuda_runtime.h>
#include <cstdint>
#include <cstddef>

// Problem constants
#define NUM_LUT 3
#define GDIM    1024      // G = IN_F / VEC
#define OUTF    4096
#define SLUT    16
#define VEC     4
#define NGRP    32        // NG = IN_F / GROUP (GROUP = 32 g's)

// Tiling: block = 8 warps; each warp owns 8 consecutive o's; block loops 8 g's.
#define NTHREADS 256
#define O_PER_WARP 8
#define OTILE (8 * O_PER_WARP)   // 64 o per block
#define GTILE_J 8                // g's per block (8 | 32 -> single quant group per block)

// Output staging tile: [64 o][stride 36 words]; row holds 8 j * 4 part = 32
// floats + 4 pad words. Stride 36 => STS bank = (o_sub*4 + part) mod 32,
// distinct for all 32 lanes of a warp (conflict-free).
#define SROW 36

// Per-LUT: local first-max argmax over this lane's 4 floats, then 2-stage quad
// bfly merge carrying (val,idx) with exact first-occurrence tie-break
// (bit-exact vs jnp.argmax). Full-warp mask: all 8 quads reduce in parallel.
#define DO_LUT(v, L, g, accv)                                              \
    {                                                                      \
        float m = (v).x; int mi = 0;                                       \
        if ((v).y > m) { m = (v).y; mi = 1; }                              \
        if ((v).z > m) { m = (v).z; mi = 2; }                              \
        if ((v).w > m) { m = (v).w; mi = 3; }                              \
        mi += part * 4;                                                    \
        _Pragma("unroll")                                                  \
        for (int d = 1; d <= 2; d <<= 1) {                                 \
            float om = __shfl_xor_sync(0xffffffffu, m,  d);                \
            int   oi = __shfl_xor_sync(0xffffffffu, mi, d);                \
            if (om > m || (om == m && oi < mi)) { m = om; mi = oi; }       \
        }                                                                  \
        (accv) += __ldg(cbk + (((size_t)(L) * GDIM + (g)) * SLUT + mi) * VEC + part); \
    }

__global__ void __launch_bounds__(NTHREADS, 8)
recon_kernel(const float* __restrict__ gate,
             const float* __restrict__ codebook,
             const float* __restrict__ scales,
             const int*   __restrict__ zeros,
             float*       __restrict__ out)
{
    __shared__ float otile[OTILE * SROW];   // 9216 B

    const int tid    = threadIdx.x;
    const int wid    = tid >> 5;
    const int lane   = tid & 31;
    const int part   = lane & 3;              // which 16B quarter of the 64B gate row
    const int o_sub  = lane >> 2;             // which of the warp's 8 o's

    const int o0_blk = blockIdx.x * OTILE;
    const int o0     = o0_blk + wid * O_PER_WARP;   // warp's first o
    const int o      = o0 + o_sub;
    const int o_loc  = wid * O_PER_WARP + o_sub;    // 0..63 within block
    const int g0     = blockIdx.y * GTILE_J;
    const int ng     = blockIdx.y >> 2;       // quant group (8*4 = 32 g's per group)

    const float sc   = scales[o * NGRP + ng];
    const float bias = -((float)zeros[o * NGRP + ng]) * sc;  // out = acc*sc + bias

    // Gate base pointers (float4 units). For fixed (l,g): warp covers
    // o0..o0+7 -> one contiguous 512B chunk; lane q reads float4 #q.
    const float4* gp0 = reinterpret_cast<const float4*>(gate) +
        (((size_t)0 * GDIM + g0) * OUTF + o0) * (SLUT / 4) + lane;
    const float4* gp1 = reinterpret_cast<const float4*>(gate) +
        (((size_t)1 * GDIM + g0) * OUTF + o0) * (SLUT / 4) + lane;
    const float4* gp2 = reinterpret_cast<const float4*>(gate) +
        (((size_t)2 * GDIM + g0) * OUTF + o0) * (SLUT / 4) + lane;
    const size_t gstep = (size_t)OUTF * SLUT / 4;   // 16384 float4 per g

    const float* cbk = codebook;

    float* myrow = &otile[o_loc * SROW + part];     // + j*4 per step

    #pragma unroll 2
    for (int j = 0; j < GTILE_J; ++j) {
        const int g = g0 + j;

        // Issue all three contiguous 512B streaming loads up front
        const float4 v0 = __ldcs(gp0 + (size_t)j * gstep);
        const float4 v1 = __ldcs(gp1 + (size_t)j * gstep);
        const float4 v2 = __ldcs(gp2 + (size_t)j * gstep);

        float acc = 0.0f;
        DO_LUT(v0, 0, g, acc)
        DO_LUT(v1, 1, g, acc)
        DO_LUT(v2, 2, g, acc)

        // Stage into smem (conflict-free); flushed coalesced at block end.
        myrow[j * 4] = fmaf(acc, sc, bias);
    }

    __syncthreads();

    // Flush: 512 float4 slots; thread t handles slots t and t+256.
    // Lanes 0..7 of each 8-lane group share one o row, j=0..7 -> one full,
    // aligned 128B global line per group: zero partial sectors, no RMW.
    #pragma unroll
    for (int t = 0; t < 2; ++t) {
        const int idx = tid + t * NTHREADS;    // 0..511
        const int ol  = idx >> 3;              // 0..63
        const int jj  = idx & 7;               // 0..7
        const float4 v = *reinterpret_cast<const float4*>(&otile[ol * SROW + jj * 4]);
        __stcs(reinterpret_cast<float4*>(out) +
               (size_t)(o0_blk + ol) * (GDIM) + g0 + jj, v);
    }
}

extern "C" void kernel_launch(void* const* d_in, const int* in_sizes, int n_in,
                              void* d_out, int out_size) {
    const float* gate     = (const float*)d_in[0];  // [3,1024,4096,16] f32
    const float* codebook = (const float*)d_in[1];  // [3,1024,16,4]   f32
    const float* scales   = (const float*)d_in[2];  // [4096,32]       f32
    const int*   zeros    = (const int*)  d_in[3];  // [4096,32]       i32
    float*       out      = (float*)d_out;          // [4096,4096]     f32

    (void)in_sizes; (void)n_in; (void)out_size;

    dim3 grid(OUTF / OTILE, GDIM / GTILE_J);   // (64, 128) = 8192 blocks
    recon_kernel<<<grid, NTHREADS>>>(gate, codebook, scales, zeros, out);
}

// round 9
// speedup vs baseline: 2.4367x; 1.0124x over previous
#include <cuda_runtime.h>
#include <cstdint>
#include <cstddef>

// Problem constants
#define NUM_LUT 3
#define GDIM    1024      // G = IN_F / VEC
#define OUTF    4096
#define SLUT    16
#define VEC     4
#define NGRP    32        // NG = IN_F / GROUP (GROUP = 32 g's)

// Tiling: block = 8 warps; each warp owns 8 consecutive o's; block loops 8 g's.
#define NTHREADS 256
#define O_PER_WARP 8
#define OTILE (8 * O_PER_WARP)   // 64 o per block
#define GTILE_J 8                // g's per block (8 | 32 -> single quant group per block)

// Output staging tile: [64 o][stride 36 words]; row holds 8 j * 4 part = 32
// floats + 4 pad words. Stride 36 => STS bank = (o_sub*4 + part) mod 32,
// distinct for all 32 lanes of a warp (conflict-free).
#define SROW 36

// Per-LUT argmax over 16 gate values spread across a quad (4 floats/lane):
//  1) exact local first-max scan over this lane's 4 values
//  2) quad max by VALUE only: 2x shfl.bfly + fmaxf (bit-exact, NaN-free data)
//  3) ballot (full-warp uniform mask) of lanes matching the quad max;
//     lowest set lane in my quad = exact first-occurrence winner
//  4) one shfl.idx fetches the winner's local index
// Bit-exact vs jnp.argmax first-index tie semantics.
#define DO_LUT(v, L, g, accv)                                                 \
    {                                                                         \
        float m = (v).x; int mi = 0;                                          \
        if ((v).y > m) { m = (v).y; mi = 1; }                                 \
        if ((v).z > m) { m = (v).z; mi = 2; }                                 \
        if ((v).w > m) { m = (v).w; mi = 3; }                                 \
        float q = fmaxf(m, __shfl_xor_sync(0xffffffffu, m, 1));               \
        q = fmaxf(q, __shfl_xor_sync(0xffffffffu, q, 2));                     \
        const unsigned bal = __ballot_sync(0xffffffffu, m == q);              \
        const unsigned nib = (bal >> (lane & 28)) & 0xFu;                     \
        const int wl = (lane & 28) + (__ffs(nib) - 1);                        \
        const int wmi = __shfl_sync(0xffffffffu, mi, wl);                     \
        const int gidx = ((wl & 3) << 2) | wmi;                               \
        (accv) += __ldg(cbk + (((size_t)(L) * GDIM + (g)) * SLUT + gidx) * VEC + part); \
    }

__global__ void __launch_bounds__(NTHREADS, 8)
recon_kernel(const float* __restrict__ gate,
             const float* __restrict__ codebook,
             const float* __restrict__ scales,
             const int*   __restrict__ zeros,
             float*       __restrict__ out)
{
    __shared__ float otile[OTILE * SROW];   // 9216 B

    const int tid    = threadIdx.x;
    const int wid    = tid >> 5;
    const int lane   = tid & 31;
    const int part   = lane & 3;              // which 16B quarter of the 64B gate row
    const int o_sub  = lane >> 2;             // which of the warp's 8 o's

    const int o0_blk = blockIdx.x * OTILE;
    const int o0     = o0_blk + wid * O_PER_WARP;   // warp's first o
    const int o      = o0 + o_sub;
    const int o_loc  = wid * O_PER_WARP + o_sub;    // 0..63 within block
    const int g0     = blockIdx.y * GTILE_J;
    const int ng     = blockIdx.y >> 2;       // quant group (8*4 = 32 g's per group)

    const float sc   = scales[o * NGRP + ng];
    const float bias = -((float)zeros[o * NGRP + ng]) * sc;  // out = acc*sc + bias

    // Gate base pointers (float4 units). For fixed (l,g): warp covers
    // o0..o0+7 -> one contiguous 512B chunk; lane q reads float4 #q.
    const float4* gp0 = reinterpret_cast<const float4*>(gate) +
        (((size_t)0 * GDIM + g0) * OUTF + o0) * (SLUT / 4) + lane;
    const float4* gp1 = reinterpret_cast<const float4*>(gate) +
        (((size_t)1 * GDIM + g0) * OUTF + o0) * (SLUT / 4) + lane;
    const float4* gp2 = reinterpret_cast<const float4*>(gate) +
        (((size_t)2 * GDIM + g0) * OUTF + o0) * (SLUT / 4) + lane;
    const size_t gstep = (size_t)OUTF * SLUT / 4;   // 16384 float4 per g

    const float* cbk = codebook;

    float* myrow = &otile[o_loc * SROW + part];     // + j*4 per step

    #pragma unroll 2
    for (int j = 0; j < GTILE_J; ++j) {
        const int g = g0 + j;

        // Issue all three contiguous 512B streaming loads up front
        const float4 v0 = __ldcs(gp0 + (size_t)j * gstep);
        const float4 v1 = __ldcs(gp1 + (size_t)j * gstep);
        const float4 v2 = __ldcs(gp2 + (size_t)j * gstep);

        float acc = 0.0f;
        DO_LUT(v0, 0, g, acc)
        DO_LUT(v1, 1, g, acc)
        DO_LUT(v2, 2, g, acc)

        // Stage into smem (conflict-free); flushed coalesced at block end.
        myrow[j * 4] = fmaf(acc, sc, bias);
    }

    __syncthreads();

    // Flush: 512 float4 slots; thread t handles slots t and t+256.
    // Lanes 0..7 of each 8-lane group share one o row, j=0..7 -> one full,
    // aligned 128B global line per group: zero partial sectors, no RMW.
    #pragma unroll
    for (int t = 0; t < 2; ++t) {
        const int idx = tid + t * NTHREADS;    // 0..511
        const int ol  = idx >> 3;              // 0..63
        const int jj  = idx & 7;               // 0..7
        const float4 v = *reinterpret_cast<const float4*>(&otile[ol * SROW + jj * 4]);
        __stcs(reinterpret_cast<float4*>(out) +
               (size_t)(o0_blk + ol) * (GDIM) + g0 + jj, v);
    }
}

extern "C" void kernel_launch(void* const* d_in, const int* in_sizes, int n_in,
                              void* d_out, int out_size) {
    const float* gate     = (const float*)d_in[0];  // [3,1024,4096,16] f32
    const float* codebook = (const float*)d_in[1];  // [3,1024,16,4]   f32
    const float* scales   = (const float*)d_in[2];  // [4096,32]       f32
    const int*   zeros    = (const int*)  d_in[3];  // [4096,32]       i32
    float*       out      = (float*)d_out;          // [4096,4096]     f32

    (void)in_sizes; (void)n_in; (void)out_size;

    dim3 grid(OUTF / OTILE, GDIM / GTILE_J);   // (64, 128) = 8192 blocks
    recon_kernel<<<grid, NTHREADS>>>(gate, codebook, scales, zeros, out);
}